// round 7
// baseline (speedup 1.0000x reference)
#include <cuda_runtime.h>
#include <cstdint>

// FeaturesLoss via mma.sync s8 m16n8k32 (int8 IMMA, exact s32 accumulation).
// Upper-triangle Gram, 128x128 tiles, 2-stage cp.async, fused loss epilogue,
// finalize fused into pair kernel via completion ticket. Exact fp32 sq-norms.

#define BM 128
#define BN 128
#define BK 64            // int8 elems (bytes) per K-chunk
#define NTHREADS 256
#define MAXN 4096
#define MAXD 512
#define SSTRB 80         // smem row stride bytes: conflict-free 16B granules

#define STAGE_OP_BYTES (BM * SSTRB)  // 10240 per operand per stage

#define QSCALE 23.0f                 // 127 / 5.52 sigma
#define INV_Q2 (1.0f / (QSCALE * QSCALE))

__device__ float g_sq[MAXN];
__device__ __align__(16) uint8_t g_Xi8[MAXN * MAXD];
__device__ double g_sum1;
__device__ double g_sum2;
__device__ unsigned long long g_cnt;
__device__ unsigned int g_done;

__device__ __forceinline__ uint32_t smem_u32(const void* p) {
    uint32_t a;
    asm("{ .reg .u64 t; cvta.to.shared.u64 t, %1; cvt.u32.u64 %0, t; }"
        : "=r"(a) : "l"(p));
    return a;
}

#define CP_ASYNC16(dst_u32, src) \
    asm volatile("cp.async.cg.shared.global [%0], [%1], 16;" :: "r"(dst_u32), "l"(src))
#define CP_COMMIT() asm volatile("cp.async.commit_group;" ::: "memory")
#define CP_WAIT0()  asm volatile("cp.async.wait_group 0;" ::: "memory")

#define LDSM_X4(r0, r1, r2, r3, a)                                        \
    asm volatile("ldmatrix.sync.aligned.m8n8.x4.shared.b16 "              \
                 "{%0,%1,%2,%3}, [%4];"                                   \
                 : "=r"(r0), "=r"(r1), "=r"(r2), "=r"(r3) : "r"(a))

#define MMA16832_S8(c, a0, a1, a2, a3, b0, b1)                            \
    asm volatile("mma.sync.aligned.m16n8k32.row.col.s32.s8.s8.s32 "       \
                 "{%0,%1,%2,%3}, {%4,%5,%6,%7}, {%8,%9}, {%0,%1,%2,%3};"  \
                 : "+r"((c)[0]), "+r"((c)[1]), "+r"((c)[2]), "+r"((c)[3]) \
                 : "r"(a0), "r"(a1), "r"(a2), "r"(a3), "r"(b0), "r"(b1))

__device__ __forceinline__ int q8(float x) {
    int v = __float2int_rn(x * QSCALE);
    return max(-127, min(127, v));
}
__device__ __forceinline__ uint32_t pack_s8x4(float4 v) {
    return (uint32_t)(q8(v.x) & 0xFF) | ((uint32_t)(q8(v.y) & 0xFF) << 8) |
           ((uint32_t)(q8(v.z) & 0xFF) << 16) | ((uint32_t)(q8(v.w) & 0xFF) << 24);
}

// ---------------------------------------------------------------------------
// Kernel A: X -> s8 + exact fp32 row norms. One warp per row, 4 rows/block.
// ---------------------------------------------------------------------------
__global__ void __launch_bounds__(128) convert_kernel(const float* __restrict__ X,
                                                      int n, int d) {
    if (blockIdx.x == 0 && threadIdx.x == 0) {
        g_sum1 = 0.0;
        g_sum2 = 0.0;
        g_cnt = 0ull;
        g_done = 0u;
    }
    const int w = threadIdx.x >> 5, l = threadIdx.x & 31;
    const int row = blockIdx.x * 4 + w;
    if (row >= n) return;
    const float4* src = reinterpret_cast<const float4*>(X + (size_t)row * d);
    uint32_t* dst = reinterpret_cast<uint32_t*>(g_Xi8 + (size_t)row * d);
    float s = 0.0f;
    if (d == 512) {  // 128 float4 per row, 4 per lane, batched loads (MLP=4)
        float4 v[4];
#pragma unroll
        for (int i = 0; i < 4; i++) v[i] = src[l + 32 * i];
#pragma unroll
        for (int i = 0; i < 4; i++) {
            s = fmaf(v[i].x, v[i].x,
                     fmaf(v[i].y, v[i].y,
                          fmaf(v[i].z, v[i].z, fmaf(v[i].w, v[i].w, s))));
            dst[l + 32 * i] = pack_s8x4(v[i]);
        }
    } else {
        for (int c4 = l; c4 * 4 < d; c4 += 32) {
            float4 v = src[c4];
            s = fmaf(v.x, v.x, fmaf(v.y, v.y, fmaf(v.z, v.z, fmaf(v.w, v.w, s))));
            dst[c4] = pack_s8x4(v);
        }
    }
#pragma unroll
    for (int o = 16; o > 0; o >>= 1) s += __shfl_down_sync(0xffffffffu, s, o);
    if (l == 0) g_sq[row] = s;
}

// ---------------------------------------------------------------------------
// Kernel B: upper-triangular int8 Gram + fused loss epilogue + final combine.
// ---------------------------------------------------------------------------
__global__ void __launch_bounds__(NTHREADS, 2) pair_kernel(
    const int* __restrict__ lab, const float* __restrict__ marginp,
    float* __restrict__ out, int n, int d, int nt, int nb) {
    __shared__ __align__(1024) uint8_t As[2][STAGE_OP_BYTES];
    __shared__ __align__(1024) uint8_t Bs[2][STAGE_OP_BYTES];
    __shared__ float sqA[BM], sqB[BN];
    __shared__ int labA[BM], labB[BN];

    const int tid = threadIdx.x;
    const int wid = tid >> 5, lane = tid & 31;
    const int warpM = wid & 3;   // 4 warps over M: 32 rows each
    const int warpN = wid >> 2;  // 2 warps over N: 64 cols each

    // Decode linear block id -> (br, bc), br <= bc.
    int b = blockIdx.x, br = 0, rl = nt;
    while (b >= rl) {
        b -= rl;
        rl--;
        br++;
    }
    const int bc = br + b;
    const int rowBase = br * BM;
    const int colBase = bc * BN;

    for (int i = tid; i < BM; i += NTHREADS) {
        sqA[i] = g_sq[rowBase + i];
        sqB[i] = g_sq[colBase + i];
        labA[i] = lab[rowBase + i];
        labB[i] = lab[colBase + i];
    }

    const uint32_t aS0 = smem_u32(&As[0][0]);
    const uint32_t bS0 = smem_u32(&Bs[0][0]);
    const uint8_t* __restrict__ Xb = g_Xi8;

    auto load_chunk = [&](int c) {
        const uint32_t aBase = aS0 + (uint32_t)(c & 1) * STAGE_OP_BYTES;
        const uint32_t bBase = bS0 + (uint32_t)(c & 1) * STAGE_OP_BYTES;
#pragma unroll
        for (int l = 0; l < 2; l++) {
            int flat = tid + l * NTHREADS;  // 0..511
            int r = flat >> 2;              // row 0..127
            int kc = flat & 3;              // 16B piece
            uint32_t off = (uint32_t)r * SSTRB + (uint32_t)kc * 16;
            const uint8_t* ga = Xb + (size_t)(rowBase + r) * d + c * BK + kc * 16;
            const uint8_t* gb = Xb + (size_t)(colBase + r) * d + c * BK + kc * 16;
            CP_ASYNC16(aBase + off, ga);
            CP_ASYNC16(bBase + off, gb);
        }
        CP_COMMIT();
    };

    int acc[2][8][4];
#pragma unroll
    for (int mt = 0; mt < 2; mt++)
#pragma unroll
        for (int ntile = 0; ntile < 8; ntile++)
#pragma unroll
            for (int e = 0; e < 4; e++) acc[mt][ntile][e] = 0;

    const uint32_t laneRow = (uint32_t)(lane & 15) * SSTRB;
    const uint32_t laneK = (uint32_t)(lane >> 4) * 16;
    const uint32_t aLane = (uint32_t)(warpM * 32) * SSTRB + laneRow + laneK;
    const uint32_t bLane = (uint32_t)(warpN * 64) * SSTRB + laneRow + laneK;

    const int nChunks = d / BK;  // 8 for d=512
    load_chunk(0);

    for (int c = 0; c < nChunks; c++) {
        CP_WAIT0();
        __syncthreads();
        if (c + 1 < nChunks) load_chunk(c + 1);

        const uint32_t aBase = aS0 + (uint32_t)(c & 1) * STAGE_OP_BYTES + aLane;
        const uint32_t bBase = bS0 + (uint32_t)(c & 1) * STAGE_OP_BYTES + bLane;

        uint32_t a[2][2][4];
#pragma unroll
        for (int mt = 0; mt < 2; mt++)
#pragma unroll
            for (int ks = 0; ks < 2; ks++)
                LDSM_X4(a[mt][ks][0], a[mt][ks][1], a[mt][ks][2], a[mt][ks][3],
                        aBase + (uint32_t)mt * 16 * SSTRB + (uint32_t)ks * 32);

#pragma unroll
        for (int ks = 0; ks < 2; ks++) {
#pragma unroll
            for (int ntp = 0; ntp < 4; ntp++) {
                uint32_t r0, r1, r2, r3;
                LDSM_X4(r0, r1, r2, r3,
                        bBase + (uint32_t)ntp * 16 * SSTRB + (uint32_t)ks * 32);
#pragma unroll
                for (int mt = 0; mt < 2; mt++) {
                    MMA16832_S8(acc[mt][2 * ntp + 0], a[mt][ks][0], a[mt][ks][1],
                                a[mt][ks][2], a[mt][ks][3], r0, r2);
                    MMA16832_S8(acc[mt][2 * ntp + 1], a[mt][ks][0], a[mt][ks][1],
                                a[mt][ks][2], a[mt][ks][3], r1, r3);
                }
            }
        }
        __syncthreads();
    }

    // Fused epilogue (layout as m16n8k16 fp variants).
    const float margin = *marginp;
    const bool diag = (br == bc);
    const float twoInv = 2.0f * INV_Q2;
    float s1 = 0.0f, s2 = 0.0f;
    unsigned int cnt = 0;
#pragma unroll
    for (int mt = 0; mt < 2; mt++) {
        const int i0 = warpM * 32 + mt * 16 + (lane >> 2);
#pragma unroll
        for (int half = 0; half < 2; half++) {
            const int iloc = i0 + half * 8;
            const int gi = rowBase + iloc;
            const float sqi = sqA[iloc];
            const int li = labA[iloc];
#pragma unroll
            for (int ntile = 0; ntile < 8; ntile++) {
#pragma unroll
                for (int e = 0; e < 2; e++) {
                    const int jloc = warpN * 64 + ntile * 8 + (lane & 3) * 2 + e;
                    const int gj = colBase + jloc;
                    float w = 2.0f;
                    if (diag) w = (gi > gj) ? 0.0f : ((gi == gj) ? 1.0f : 2.0f);
                    if (w != 0.0f) {
                        float D = sqi + sqB[jloc] -
                                  twoInv * (float)acc[mt][ntile][half * 2 + e];
                        D = fmaxf(D, 0.0f);
                        if (li == labB[jloc]) {
                            s1 += w * D;
                            cnt += (unsigned int)w;
                        } else {
                            s2 += w * fmaxf(0.0f, margin - D);
                        }
                    }
                }
            }
        }
    }

    // Block reduction -> double atomics.
#pragma unroll
    for (int o = 16; o > 0; o >>= 1) {
        s1 += __shfl_down_sync(0xffffffffu, s1, o);
        s2 += __shfl_down_sync(0xffffffffu, s2, o);
        cnt += __shfl_down_sync(0xffffffffu, cnt, o);
    }
    __shared__ float r1[8], r2[8];
    __shared__ unsigned int rc[8];
    if (lane == 0) {
        r1[wid] = s1;
        r2[wid] = s2;
        rc[wid] = cnt;
    }
    __syncthreads();
    if (tid == 0) {
        double t1 = 0.0, t2 = 0.0;
        unsigned int tc = 0;
#pragma unroll
        for (int w = 0; w < 8; w++) {
            t1 += (double)r1[w];
            t2 += (double)r2[w];
            tc += rc[w];
        }
        atomicAdd(&g_sum1, t1);
        atomicAdd(&g_sum2, t2);
        atomicAdd(&g_cnt, (unsigned long long)tc);

        // Completion ticket: last CTA combines and resets for graph replay.
        __threadfence();
        unsigned int old = atomicAdd(&g_done, 1u);
        if (old == (unsigned int)(nb - 1)) {
            double zn1 = (double)atomicAdd(&g_cnt, 0ull);
            double t1f = atomicAdd(&g_sum1, 0.0);
            double t2f = atomicAdd(&g_sum2, 0.0);
            double zn2 = (double)n * (double)n - zn1;
            out[0] = (float)(0.5 * (t1f / zn1 + t2f / zn2));
            g_done = 0u;
        }
    }
}

extern "C" void kernel_launch(void* const* d_in, const int* in_sizes, int n_in,
                              void* d_out, int out_size) {
    const float* X = (const float*)d_in[0];
    const int* lab = (const int*)d_in[1];
    const float* marginp = (const float*)d_in[2];
    float* out = (float*)d_out;

    int n = in_sizes[1];
    int d = in_sizes[0] / n;

    convert_kernel<<<(n + 3) / 4, 128>>>(X, n, d);

    int nt = (n + BM - 1) / BM;
    int nb = nt * (nt + 1) / 2;
    pair_kernel<<<nb, NTHREADS>>>(lab, marginp, out, n, d, nt, nb);
}

// round 8
// speedup vs baseline: 1.7007x; 1.7007x over previous
#include <cuda_runtime.h>
#include <cstdint>

// FeaturesLoss via mma.sync e4m3 m16n8k32 (compute_103-safe), persistent CTAs.
// Upper-triangle Gram streamed as flat (tile,chunk) sequence through a 3-stage
// cp.async ring (2 chunks in flight), fused loss epilogue, fused finalize.

#define BM 128
#define BN 128
#define BK 64            // fp8 bytes per K-chunk
#define NTHREADS 256
#define MAXN 4096
#define MAXD 512
#define SSTRB 80         // smem row stride bytes: conflict-free 16B granules
#define NSTG 3

#define STAGE_OP_BYTES (BM * SSTRB)          // 10240 per operand per stage
#define SM_A 0
#define SM_B (NSTG * STAGE_OP_BYTES)          // 30720
#define SM_SQA (2 * NSTG * STAGE_OP_BYTES)    // 61440
#define SM_SQB (SM_SQA + 512)
#define SM_LABA (SM_SQB + 512)
#define SM_LABB (SM_LABA + 512)
#define SM_RED (SM_LABB + 512)
#define SMEM_TOTAL (SM_RED + 128)             // 63616

__device__ float g_sq[MAXN];
__device__ __align__(16) uint8_t g_Xf8[MAXN * MAXD];
__device__ double g_sum1;
__device__ double g_sum2;
__device__ unsigned long long g_cnt;
__device__ unsigned int g_done;

__device__ __forceinline__ uint32_t smem_u32(const void* p) {
    uint32_t a;
    asm("{ .reg .u64 t; cvta.to.shared.u64 t, %1; cvt.u32.u64 %0, t; }"
        : "=r"(a) : "l"(p));
    return a;
}

#define CP_ASYNC16(dst_u32, src) \
    asm volatile("cp.async.cg.shared.global [%0], [%1], 16;" :: "r"(dst_u32), "l"(src))
#define CP_COMMIT() asm volatile("cp.async.commit_group;" ::: "memory")
#define CP_WAIT1()  asm volatile("cp.async.wait_group 1;" ::: "memory")

#define LDSM_X4(r0, r1, r2, r3, a)                                        \
    asm volatile("ldmatrix.sync.aligned.m8n8.x4.shared.b16 "              \
                 "{%0,%1,%2,%3}, [%4];"                                   \
                 : "=r"(r0), "=r"(r1), "=r"(r2), "=r"(r3) : "r"(a))

#define MMA16832(c, a0, a1, a2, a3, b0, b1)                               \
    asm volatile("mma.sync.aligned.m16n8k32.row.col.f32.e4m3.e4m3.f32 "   \
                 "{%0,%1,%2,%3}, {%4,%5,%6,%7}, {%8,%9}, {%0,%1,%2,%3};"  \
                 : "+f"((c)[0]), "+f"((c)[1]), "+f"((c)[2]), "+f"((c)[3]) \
                 : "r"(a0), "r"(a1), "r"(a2), "r"(a3), "r"(b0), "r"(b1))

__device__ __forceinline__ uint32_t pack_e4m3x4(float4 v) {
    uint16_t lo, hi;
    asm("cvt.rn.satfinite.e4m3x2.f32 %0, %1, %2;" : "=h"(lo) : "f"(v.y), "f"(v.x));
    asm("cvt.rn.satfinite.e4m3x2.f32 %0, %1, %2;" : "=h"(hi) : "f"(v.w), "f"(v.z));
    return (uint32_t)lo | ((uint32_t)hi << 16);
}

__device__ __forceinline__ void decode_tile(int t, int nt, int& br, int& bc) {
    int b = t, r = 0, rl = nt;
    while (b >= rl) {
        b -= rl;
        rl--;
        r++;
    }
    br = r;
    bc = r + b;
}

// ---------------------------------------------------------------------------
// Kernel A: X -> e4m3 + exact fp32 row norms. One warp per row.
// ---------------------------------------------------------------------------
__global__ void __launch_bounds__(128) convert_kernel(const float* __restrict__ X,
                                                      int n, int d) {
    if (blockIdx.x == 0 && threadIdx.x == 0) {
        g_sum1 = 0.0;
        g_sum2 = 0.0;
        g_cnt = 0ull;
        g_done = 0u;
    }
    const int w = threadIdx.x >> 5, l = threadIdx.x & 31;
    const int row = blockIdx.x * 4 + w;
    if (row >= n) return;
    const float4* src = reinterpret_cast<const float4*>(X + (size_t)row * d);
    uint32_t* dst = reinterpret_cast<uint32_t*>(g_Xf8 + (size_t)row * d);
    float s = 0.0f;
    if (d == 512) {
        float4 v[4];
#pragma unroll
        for (int i = 0; i < 4; i++) v[i] = src[l + 32 * i];
#pragma unroll
        for (int i = 0; i < 4; i++) {
            s = fmaf(v[i].x, v[i].x,
                     fmaf(v[i].y, v[i].y,
                          fmaf(v[i].z, v[i].z, fmaf(v[i].w, v[i].w, s))));
            dst[l + 32 * i] = pack_e4m3x4(v[i]);
        }
    } else {
        for (int c4 = l; c4 * 4 < d; c4 += 32) {
            float4 v = src[c4];
            s = fmaf(v.x, v.x, fmaf(v.y, v.y, fmaf(v.z, v.z, fmaf(v.w, v.w, s))));
            dst[c4] = pack_e4m3x4(v);
        }
    }
#pragma unroll
    for (int o = 16; o > 0; o >>= 1) s += __shfl_down_sync(0xffffffffu, s, o);
    if (l == 0) g_sq[row] = s;
}

// ---------------------------------------------------------------------------
// Kernel B: persistent fp8 Gram over tile stream + fused epilogue + finalize.
// ---------------------------------------------------------------------------
__global__ void __launch_bounds__(NTHREADS, 2) pair_kernel(
    const int* __restrict__ lab, const float* __restrict__ marginp,
    float* __restrict__ out, int n, int d, int nt, int nb) {
    extern __shared__ __align__(1024) uint8_t smem[];
    const uint32_t sbase = smem_u32(smem);
    float* sqA = reinterpret_cast<float*>(smem + SM_SQA);
    float* sqB = reinterpret_cast<float*>(smem + SM_SQB);
    int* labA = reinterpret_cast<int*>(smem + SM_LABA);
    int* labB = reinterpret_cast<int*>(smem + SM_LABB);

    const int tid = threadIdx.x;
    const int wid = tid >> 5, lane = tid & 31;
    const int warpM = wid & 3;   // 4 warps over M: 32 rows each
    const int warpN = wid >> 2;  // 2 warps over N: 64 cols each

    const int nChunks = d / BK;  // 8 for d=512
    const int stride = gridDim.x;
    int myTiles = 0;
    for (int t = blockIdx.x; t < nb; t += stride) myTiles++;
    const int total = myTiles * nChunks;

    const uint8_t* __restrict__ Xb = g_Xf8;
    const float margin = *marginp;

    // Issue one chunk load (BK=64 bytes per row) into stage slot.
    auto load_chunk = [&](int rb, int cb, int c, int slot) {
        const uint32_t aBase = sbase + SM_A + (uint32_t)slot * STAGE_OP_BYTES;
        const uint32_t bBase = sbase + SM_B + (uint32_t)slot * STAGE_OP_BYTES;
        const int rowB = rb * BM, colB = cb * BN;
#pragma unroll
        for (int l = 0; l < 2; l++) {
            int flat = tid + l * NTHREADS;  // 0..511
            int r = flat >> 2;              // row 0..127
            int kc = flat & 3;              // 16B piece
            uint32_t off = (uint32_t)r * SSTRB + (uint32_t)kc * 16;
            const uint8_t* ga = Xb + (size_t)(rowB + r) * d + c * BK + kc * 16;
            const uint8_t* gb = Xb + (size_t)(colB + r) * d + c * BK + kc * 16;
            CP_ASYNC16(aBase + off, ga);
            CP_ASYNC16(bBase + off, gb);
        }
    };

    float acc[2][8][4];
#pragma unroll
    for (int mt = 0; mt < 2; mt++)
#pragma unroll
        for (int ntile = 0; ntile < 8; ntile++)
#pragma unroll
            for (int e = 0; e < 4; e++) acc[mt][ntile][e] = 0.0f;

    const uint32_t laneRow = (uint32_t)(lane & 15) * SSTRB;
    const uint32_t laneK = (uint32_t)(lane >> 4) * 16;
    const uint32_t aLane = (uint32_t)(warpM * 32) * SSTRB + laneRow + laneK;
    const uint32_t bLane = (uint32_t)(warpN * 64) * SSTRB + laneRow + laneK;

    // Cross-tile running sums (registers).
    float s1 = 0.0f, s2 = 0.0f;
    unsigned int cnt = 0;

    // Compute-stream tile state and load-stream tile state.
    int cpK = 0, cpRB = 0, cpCB = 0;
    int ldK = 0, ldRB = 0, ldCB = 0;
    if (myTiles > 0) {
        decode_tile(blockIdx.x, nt, cpRB, cpCB);
        ldRB = cpRB;
        ldCB = cpCB;
    }

    // Prefetch global chunks 0 and 1 (both in tile 0 since nChunks >= 2).
#pragma unroll
    for (int p = 0; p < 2; p++) {
        if (p < total) load_chunk(ldRB, ldCB, p, p % NSTG);
        CP_COMMIT();
    }

    for (int gs = 0; gs < total; gs++) {
        const int c = gs & (nChunks - 1);
        CP_WAIT1();      // commits so far = gs+2; <=1 pending => chunk gs done
        __syncthreads();

        if (c == 0) {  // stage metadata for the tile we're about to compute
            int i = tid & 127;
            if (tid < 128) {
                sqA[i] = g_sq[cpRB * BM + i];
                labA[i] = lab[cpRB * BM + i];
            } else {
                sqB[i] = g_sq[cpCB * BN + i];
                labB[i] = lab[cpCB * BN + i];
            }
        }

        const int gl = gs + 2;
        if (gl < total) {
            const int lk = gl / nChunks;
            if (lk != ldK) {
                ldK = lk;
                decode_tile(blockIdx.x + lk * stride, nt, ldRB, ldCB);
            }
            load_chunk(ldRB, ldCB, gl & (nChunks - 1), gl % NSTG);
        }
        CP_COMMIT();  // always commit (possibly empty) to keep counts aligned

        const uint32_t stBase = (uint32_t)(gs % NSTG) * STAGE_OP_BYTES;
        const uint32_t aBase = sbase + SM_A + stBase + aLane;
        const uint32_t bBase = sbase + SM_B + stBase + bLane;

        uint32_t a[2][2][4];
#pragma unroll
        for (int mt = 0; mt < 2; mt++)
#pragma unroll
            for (int ks = 0; ks < 2; ks++)
                LDSM_X4(a[mt][ks][0], a[mt][ks][1], a[mt][ks][2], a[mt][ks][3],
                        aBase + (uint32_t)mt * 16 * SSTRB + (uint32_t)ks * 32);

#pragma unroll
        for (int ks = 0; ks < 2; ks++) {
#pragma unroll
            for (int ntp = 0; ntp < 4; ntp++) {
                uint32_t r0, r1, r2, r3;
                LDSM_X4(r0, r1, r2, r3,
                        bBase + (uint32_t)ntp * 16 * SSTRB + (uint32_t)ks * 32);
#pragma unroll
                for (int mt = 0; mt < 2; mt++) {
                    MMA16832(acc[mt][2 * ntp + 0], a[mt][ks][0], a[mt][ks][1],
                             a[mt][ks][2], a[mt][ks][3], r0, r2);
                    MMA16832(acc[mt][2 * ntp + 1], a[mt][ks][0], a[mt][ks][1],
                             a[mt][ks][2], a[mt][ks][3], r1, r3);
                }
            }
        }

        if (c == nChunks - 1) {
            // Fused epilogue for tile cpK; accumulate into running sums.
            const int rowBase = cpRB * BM, colBase = cpCB * BN;
            const bool diag = (cpRB == cpCB);
#pragma unroll
            for (int mt = 0; mt < 2; mt++) {
                const int i0 = warpM * 32 + mt * 16 + (lane >> 2);
#pragma unroll
                for (int half = 0; half < 2; half++) {
                    const int iloc = i0 + half * 8;
                    const int gi = rowBase + iloc;
                    const float sqi = sqA[iloc];
                    const int li = labA[iloc];
#pragma unroll
                    for (int ntile = 0; ntile < 8; ntile++) {
#pragma unroll
                        for (int e = 0; e < 2; e++) {
                            const int jloc =
                                warpN * 64 + ntile * 8 + (lane & 3) * 2 + e;
                            const int gj = colBase + jloc;
                            float w = 2.0f;
                            if (diag)
                                w = (gi > gj) ? 0.0f : ((gi == gj) ? 1.0f : 2.0f);
                            if (w != 0.0f) {
                                float D = sqi + sqB[jloc] -
                                          2.0f * acc[mt][ntile][half * 2 + e];
                                D = fmaxf(D, 0.0f);
                                if (li == labB[jloc]) {
                                    s1 += w * D;
                                    cnt += (unsigned int)w;
                                } else {
                                    s2 += w * fmaxf(0.0f, margin - D);
                                }
                            }
                            acc[mt][ntile][half * 2 + e] = 0.0f;
                        }
                    }
                }
            }
            cpK++;
            if (cpK < myTiles)
                decode_tile(blockIdx.x + cpK * stride, nt, cpRB, cpCB);
        }
    }

    // One block reduction + atomics per CTA.
#pragma unroll
    for (int o = 16; o > 0; o >>= 1) {
        s1 += __shfl_down_sync(0xffffffffu, s1, o);
        s2 += __shfl_down_sync(0xffffffffu, s2, o);
        cnt += __shfl_down_sync(0xffffffffu, cnt, o);
    }
    float* r1 = reinterpret_cast<float*>(smem + SM_RED);
    float* r2 = r1 + 8;
    unsigned int* rc = reinterpret_cast<unsigned int*>(r2 + 8);
    __syncthreads();
    if (lane == 0) {
        r1[wid] = s1;
        r2[wid] = s2;
        rc[wid] = cnt;
    }
    __syncthreads();
    if (tid == 0) {
        double t1 = 0.0, t2 = 0.0;
        unsigned int tc = 0;
#pragma unroll
        for (int w = 0; w < 8; w++) {
            t1 += (double)r1[w];
            t2 += (double)r2[w];
            tc += rc[w];
        }
        atomicAdd(&g_sum1, t1);
        atomicAdd(&g_sum2, t2);
        atomicAdd(&g_cnt, (unsigned long long)tc);

        __threadfence();
        unsigned int old = atomicAdd(&g_done, 1u);
        if (old == gridDim.x - 1) {
            double zn1 = (double)atomicAdd(&g_cnt, 0ull);
            double t1f = atomicAdd(&g_sum1, 0.0);
            double t2f = atomicAdd(&g_sum2, 0.0);
            double zn2 = (double)n * (double)n - zn1;
            out[0] = (float)(0.5 * (t1f / zn1 + t2f / zn2));
            g_done = 0u;
        }
    }
}

extern "C" void kernel_launch(void* const* d_in, const int* in_sizes, int n_in,
                              void* d_out, int out_size) {
    const float* X = (const float*)d_in[0];
    const int* lab = (const int*)d_in[1];
    const float* marginp = (const float*)d_in[2];
    float* out = (float*)d_out;

    int n = in_sizes[1];
    int d = in_sizes[0] / n;

    cudaFuncSetAttribute(pair_kernel,
                         cudaFuncAttributeMaxDynamicSharedMemorySize, SMEM_TOTAL);

    convert_kernel<<<(n + 3) / 4, 128>>>(X, n, d);

    int nt = (n + BM - 1) / BM;
    int nb = nt * (nt + 1) / 2;
    int ctas = nb < 296 ? nb : 296;  // 2 persistent CTAs per SM (148 SMs)
    pair_kernel<<<ctas, NTHREADS, SMEM_TOTAL>>>(lab, marginp, out, n, d, nt, nb);
}